// round 5
// baseline (speedup 1.0000x reference)
#include <cuda_runtime.h>
#include <math.h>

#define NTOT 2048          // B*N
#define KSEL 20

__device__ float  g_part[2 * NTOT * 512]; // K-split partial GEMM results
__device__ float  g_xlxr[NTOT * 512];     // [g][0:256)=xl, [256:512)=xr
__device__ float2 g_xrP[4 * 128 * 512];   // [b][d2][j] = (xr[j][2d2], xr[j][2d2+1])
__device__ float  g_alpha[NTOT * 512];
__device__ float  g_L[NTOT];
__device__ float  g_R[NTOT];

// ---------------- packed f32x2 helpers ----------------
__device__ __forceinline__ double fma2(double a, double b, double c) {
    double d;
    asm("fma.rn.f32x2 %0, %1, %2, %3;" : "=d"(d) : "d"(a), "d"(b), "d"(c));
    return d;
}
__device__ __forceinline__ double add2(double a, double b) {
    double d;
    asm("add.rn.f32x2 %0, %1, %2;" : "=d"(d) : "d"(a), "d"(b));
    return d;
}
__device__ __forceinline__ double abs2(double a) {
    return __longlong_as_double(__double_as_longlong(a) & 0x7fffffff7fffffffULL);
}
__device__ __forceinline__ double dup2(float v) {
    double d;
    asm("mov.b64 %0, {%1, %1};" : "=d"(d) : "f"(v));
    return d;
}
__device__ __forceinline__ float2 unpack2(double a) {
    float2 f;
    asm("mov.b64 {%0, %1}, %2;" : "=f"(f.x), "=f"(f.y) : "d"(a));
    return f;
}
__device__ __forceinline__ unsigned redux_max_u32(unsigned v) {
    unsigned r;
    asm("redux.sync.max.u32 %0, %1, 0xffffffff;" : "=r"(r) : "r"(v));
    return r;
}

// ---------------------------------------------------------------------------
// Kernel 1: K-split projection GEMM. 64x64 tile, BK=16, double-buffered smem.
// ---------------------------------------------------------------------------
__global__ __launch_bounds__(256) void proj_kernel(
    const float* __restrict__ x,
    const float* __restrict__ Wl, const float* __restrict__ bl,
    const float* __restrict__ Wr, const float* __restrict__ br)
{
    __shared__ __align__(16) float As2[2][16 * 132];  // [stage][k][2m] dup pairs
    __shared__ __align__(16) float Bs[2][16 * 68];    // [stage][k][n]
    const int tid = threadIdx.x;
    const int tx = tid & 15, ty = tid >> 4;
    const int g0 = blockIdx.x * 64;
    const int n0 = blockIdx.y * 64;
    const int kh = blockIdx.z;
    const float* W    = (n0 < 256) ? Wl : Wr;
    const float* bias = (n0 < 256) ? bl : br;
    const int nw0 = (n0 < 256) ? n0 : n0 - 256;

    const int lm = tid >> 2;
    const int lk = (tid & 3) << 2;

    double acc[4][2];
#pragma unroll
    for (int i = 0; i < 4; ++i) { acc[i][0] = 0.0; acc[i][1] = 0.0; }

    const float* xp = &x[(g0 + lm) * 256 + kh * 128 + lk];
    const float* wp = &W[(nw0 + lm) * 256 + kh * 128 + lk];

    float4 av = *(const float4*)xp;
    float4 bv = *(const float4*)wp;
    {
        float* A = As2[0]; float* B = Bs[0];
        *(double*)&A[(lk + 0) * 132 + 2 * lm] = dup2(av.x);
        *(double*)&A[(lk + 1) * 132 + 2 * lm] = dup2(av.y);
        *(double*)&A[(lk + 2) * 132 + 2 * lm] = dup2(av.z);
        *(double*)&A[(lk + 3) * 132 + 2 * lm] = dup2(av.w);
        B[(lk + 0) * 68 + lm] = bv.x; B[(lk + 1) * 68 + lm] = bv.y;
        B[(lk + 2) * 68 + lm] = bv.z; B[(lk + 3) * 68 + lm] = bv.w;
    }
    av = *(const float4*)(xp + 16);
    bv = *(const float4*)(wp + 16);

#pragma unroll 1
    for (int t = 0; t < 8; ++t) {
        __syncthreads();
        if (t < 7) {
            float* A = As2[(t + 1) & 1]; float* B = Bs[(t + 1) & 1];
            *(double*)&A[(lk + 0) * 132 + 2 * lm] = dup2(av.x);
            *(double*)&A[(lk + 1) * 132 + 2 * lm] = dup2(av.y);
            *(double*)&A[(lk + 2) * 132 + 2 * lm] = dup2(av.z);
            *(double*)&A[(lk + 3) * 132 + 2 * lm] = dup2(av.w);
            B[(lk + 0) * 68 + lm] = bv.x; B[(lk + 1) * 68 + lm] = bv.y;
            B[(lk + 2) * 68 + lm] = bv.z; B[(lk + 3) * 68 + lm] = bv.w;
        }
        if (t < 6) {
            av = *(const float4*)(xp + (t + 2) * 16);
            bv = *(const float4*)(wp + (t + 2) * 16);
        }
        const float* A = As2[t & 1]; const float* B = Bs[t & 1];
#pragma unroll
        for (int k = 0; k < 16; ++k) {
            const double2 alo = *(const double2*)&A[k * 132 + 8 * ty];
            const double2 ahi = *(const double2*)&A[k * 132 + 8 * ty + 4];
            const double2 b2  = *(const double2*)&B[k * 68 + 4 * tx];
            acc[0][0] = fma2(alo.x, b2.x, acc[0][0]);
            acc[0][1] = fma2(alo.x, b2.y, acc[0][1]);
            acc[1][0] = fma2(alo.y, b2.x, acc[1][0]);
            acc[1][1] = fma2(alo.y, b2.y, acc[1][1]);
            acc[2][0] = fma2(ahi.x, b2.x, acc[2][0]);
            acc[2][1] = fma2(ahi.x, b2.y, acc[2][1]);
            acc[3][0] = fma2(ahi.y, b2.x, acc[3][0]);
            acc[3][1] = fma2(ahi.y, b2.y, acc[3][1]);
        }
    }

    float* dst = g_part + (size_t)kh * NTOT * 512;
#pragma unroll
    for (int i = 0; i < 4; ++i) {
        const int row = g0 + ty * 4 + i;
        const float2 p0 = unpack2(acc[i][0]);
        const float2 p1 = unpack2(acc[i][1]);
        float4 o;
        if (kh == 0) {
            o.x = p0.x + bias[nw0 + tx * 4 + 0];
            o.y = p0.y + bias[nw0 + tx * 4 + 1];
            o.z = p1.x + bias[nw0 + tx * 4 + 2];
            o.w = p1.y + bias[nw0 + tx * 4 + 3];
        } else {
            o.x = p0.x; o.y = p0.y; o.z = p1.x; o.w = p1.y;
        }
        *(float4*)&dst[row * 512 + n0 + tx * 4] = o;
    }
}

// ---------------------------------------------------------------------------
// Kernel 2: finalize. Sum K-partials -> g_xlxr; L/R dots; xr transpose.
// ---------------------------------------------------------------------------
#define SLAB_S 524
#define FIN_SMEM ((32 * SLAB_S + 256) * 4)

__global__ __launch_bounds__(256) void finalize_kernel(const float* __restrict__ att)
{
    extern __shared__ float sh[];
    float* slab  = sh;                 // [32][SLAB_S]
    float* att_s = sh + 32 * SLAB_S;   // [256]
    const int tid = threadIdx.x;
    const int g0 = blockIdx.x * 32;
    const int b = g0 >> 9;
    const int j0b = g0 & 511;

    att_s[tid] = att[tid];
#pragma unroll
    for (int p = 0; p < 16; ++p) {
        const int idx = p * 256 + tid;
        const int row = idx >> 7, c4 = idx & 127;
        const size_t ga = (size_t)(g0 + row) * 512 + c4 * 4;
        float4 a = *(const float4*)&g_part[ga];
        const float4 c = *(const float4*)&g_part[(size_t)NTOT * 512 + ga];
        a.x += c.x; a.y += c.y; a.z += c.z; a.w += c.w;
        *(float4*)&g_xlxr[ga] = a;
        *(float4*)&slab[row * SLAB_S + c4 * 4] = a;
    }
    __syncthreads();

    const int w = tid >> 5, l = tid & 31;
#pragma unroll
    for (int p = 0; p < 8; ++p) {
        const int id = p * 8 + w;
        const int row = id >> 1, half = id & 1;
        float s = 0.f;
#pragma unroll
        for (int q = 0; q < 8; ++q)
            s += att_s[l + 32 * q] * slab[row * SLAB_S + half * 256 + l + 32 * q];
#pragma unroll
        for (int off = 16; off; off >>= 1) s += __shfl_xor_sync(0xffffffffu, s, off);
        if (l == 0) {
            if (half) g_R[g0 + row] = 0.6f * s;
            else      g_L[g0 + row] = 0.6f * s;
        }
    }

#pragma unroll
    for (int p = 0; p < 16; ++p) {
        const int idx = p * 256 + tid;
        const int d2 = idx >> 5, jl = idx & 31;
        const float2 v = *(const float2*)&slab[jl * SLAB_S + 256 + 2 * d2];
        g_xrP[((size_t)b * 128 + d2) * 512 + j0b + jl] = v;
    }
}

// ---------------------------------------------------------------------------
// Kernel 3: pairwise scores. Lane owns j; warp group owns 8 i-rows.
// 8-double xr chunks to fit 4 blocks/SM (single wave at grid 512).
// ---------------------------------------------------------------------------
__global__ __launch_bounds__(256, 4) void pair_kernel(const float* __restrict__ att)
{
    __shared__ float xl[16 * 256];
    __shared__ float ws[256];
    __shared__ float Ls[16];

    const int tid = threadIdx.x;
    const int g0 = blockIdx.x * 16;
    const int b512 = g0 & ~511;
    const int jq = blockIdx.y;

    ws[tid] = 0.4f * att[tid];
#pragma unroll
    for (int q = 0; q < 4; ++q) {
        const int idx = tid + q * 256;
        const int row = idx >> 6, c4 = idx & 63;
        *(float4*)&xl[row * 256 + c4 * 4] =
            *(const float4*)&g_xlxr[(size_t)(g0 + row) * 512 + c4 * 4];
    }
    if (tid < 16) Ls[tid] = g_L[g0 + tid];
    __syncthreads();

    const int w = tid >> 5, l = tid & 31;
    const int grp = w >> 2;
    const int jsl = w & 3;
    const int jj = jq * 128 + jsl * 32 + l;
    const float Rj = g_R[b512 + jj];
    const double* __restrict__ xrp = (const double*)g_xrP + (size_t)(b512 >> 9) * 128 * 512;

    double acc[8];
#pragma unroll
    for (int i = 0; i < 8; ++i) acc[i] = 0.0;

#pragma unroll 1
    for (int ch = 0; ch < 16; ++ch) {  // chunks of 16 d (8 d-pairs)
        double xr[8];
#pragma unroll
        for (int q = 0; q < 8; ++q)
            xr[q] = xrp[(size_t)(ch * 8 + q) * 512 + jj];
#pragma unroll
        for (int i = 0; i < 8; ++i) {
            const float* xlr = xl + (grp * 8 + i) * 256 + ch * 16;
            const float* wsr = ws + ch * 16;
            double a = acc[i];
#pragma unroll
            for (int q2 = 0; q2 < 4; ++q2) {
                const double2 av = *(const double2*)(xlr + q2 * 4);
                const double2 wv = *(const double2*)(wsr + q2 * 4);
                const double t0 = add2(av.x, xr[2 * q2]);
                const double t1 = add2(av.y, xr[2 * q2 + 1]);
                a = fma2(wv.x, abs2(t0), a);
                a = fma2(wv.y, abs2(t1), a);
            }
            acc[i] = a;
        }
    }
#pragma unroll
    for (int i = 0; i < 8; ++i) {
        const float2 p = unpack2(acc[i]);
        const int r = grp * 8 + i;
        g_alpha[(size_t)(g0 + r) * 512 + jj] = Ls[r] + Rj + (p.x + p.y);
    }
}

// ---------------------------------------------------------------------------
// Kernel 4: top-20 + softmax. Warp per row. Per-lane 16-key sort network once,
// then 20 rounds of redux-based argmax with O(1) owner pop from private smem.
// ---------------------------------------------------------------------------
__global__ __launch_bounds__(256) void topk_kernel(float* __restrict__ out)
{
    __shared__ unsigned long long skey[8][17][32];  // [warp][slot][lane]
    const int tid = threadIdx.x;
    const int w = tid >> 5, l = tid & 31;
    const int g = blockIdx.x * 8 + w;
    const float* __restrict__ arow = g_alpha + (size_t)g * 512;

    // build sortable keys: hi = monotone(float), lo = 511 - j  (tie -> lower j)
    unsigned long long k[16];
#pragma unroll
    for (int t = 0; t < 16; ++t) {
        const int j = l + 32 * t;
        const unsigned u = __float_as_uint(arow[j]);
        const unsigned s = ((int)u < 0) ? ~u : (u | 0x80000000u);
        k[t] = ((unsigned long long)s << 32) | (unsigned)(511 - j);
    }

    // Batcher odd-even mergesort, descending, n=16 (fully unrolled)
#pragma unroll
    for (int p = 1; p < 16; p <<= 1) {
#pragma unroll
        for (int q = p; q >= 1; q >>= 1) {
#pragma unroll
            for (int jx = q % p; jx <= 15 - q; jx += 2 * q) {
#pragma unroll
                for (int ix = 0; ix < q; ++ix) {
                    if (ix + jx + q <= 15 &&
                        (ix + jx) / (2 * p) == (ix + jx + q) / (2 * p)) {
                        const int a = ix + jx, bq = ix + jx + q;
                        if (k[a] < k[bq]) {
                            const unsigned long long tmp = k[a];
                            k[a] = k[bq]; k[bq] = tmp;
                        }
                    }
                }
            }
        }
    }

    // spill sorted list (own lane column only; no cross-lane reads -> no sync)
#pragma unroll
    for (int t = 0; t < 16; ++t) skey[w][t][l] = k[t];
    skey[w][16][l] = 0ull;                     // sentinel (below all finite)

    unsigned hi = (unsigned)(k[0] >> 32);
    unsigned lo = (unsigned)k[0];
    int ptr = 1;

    unsigned sel_hi = 0, sel_lo = 0;
    for (int kk = 0; kk < KSEL; ++kk) {
        const unsigned m  = redux_max_u32(hi);
        const unsigned lc = (hi == m) ? lo : 0u;
        const unsigned lm = redux_max_u32(lc);   // max(511-j) = min j among ties
        if (l == kk) { sel_hi = m; sel_lo = lm; }
        if (hi == m && lo == lm) {               // unique owner pops next
            const unsigned long long nk = skey[w][ptr][l];
            ++ptr;
            hi = (unsigned)(nk >> 32);
            lo = (unsigned)nk;
        }
    }

    // decode value, softmax over the 20 selected (lane 0 holds the max)
    const unsigned ub = (sel_hi & 0x80000000u) ? (sel_hi & 0x7fffffffu) : ~sel_hi;
    const float val = __uint_as_float(ub);
    const float m0 = __shfl_sync(0xffffffffu, val, 0);
    const float e = (l < KSEL) ? expf(val - m0) : 0.f;
    float s = e;
#pragma unroll
    for (int off = 16; off; off >>= 1) s += __shfl_xor_sync(0xffffffffu, s, off);
    if (l < KSEL) {
        const int base = g * KSEL + l;
        const int j = 511 - (int)sel_lo;
        out[base]                   = (float)g;                  // index_i
        out[NTOT * KSEL + base]     = (float)((g & ~511) + j);   // index_j
        out[2 * NTOT * KSEL + base] = e / s;                     // attention
    }
}

// ---------------------------------------------------------------------------
extern "C" void kernel_launch(void* const* d_in, const int* in_sizes, int n_in,
                              void* d_out, int out_size)
{
    const float* x   = (const float*)d_in[0];
    const float* Wl  = (const float*)d_in[3];
    const float* bl  = (const float*)d_in[4];
    const float* Wr  = (const float*)d_in[5];
    const float* br  = (const float*)d_in[6];
    const float* att = (const float*)d_in[7];
    float* out = (float*)d_out;

    proj_kernel<<<dim3(32, 8, 2), 256>>>(x, Wl, bl, Wr, br);
    cudaFuncSetAttribute(finalize_kernel,
                         cudaFuncAttributeMaxDynamicSharedMemorySize, FIN_SMEM);
    finalize_kernel<<<64, 256, FIN_SMEM>>>(att);
    pair_kernel<<<dim3(128, 4), 256>>>(att);
    topk_kernel<<<256, 256>>>(out);
}

// round 6
// speedup vs baseline: 1.0287x; 1.0287x over previous
#include <cuda_runtime.h>
#include <math.h>

#define NTOT 2048          // B*N
#define KSEL 20

__device__ float  g_part[2 * NTOT * 512]; // K-split partial GEMM results
__device__ float  g_xlxr[NTOT * 512];     // [g][0:256)=xl, [256:512)=xr
__device__ float  g_xrT[4 * 256 * 512];   // [b][d][j] transposed xr
__device__ float  g_L[NTOT];
__device__ float  g_R[NTOT];

// ---------------- packed f32x2 helpers ----------------
__device__ __forceinline__ double fma2(double a, double b, double c) {
    double d;
    asm("fma.rn.f32x2 %0, %1, %2, %3;" : "=d"(d) : "d"(a), "d"(b), "d"(c));
    return d;
}
__device__ __forceinline__ double add2(double a, double b) {
    double d;
    asm("add.rn.f32x2 %0, %1, %2;" : "=d"(d) : "d"(a), "d"(b));
    return d;
}
__device__ __forceinline__ double abs2(double a) {
    return __longlong_as_double(__double_as_longlong(a) & 0x7fffffff7fffffffULL);
}
__device__ __forceinline__ double dup2(float v) {
    double d;
    asm("mov.b64 %0, {%1, %1};" : "=d"(d) : "f"(v));
    return d;
}
__device__ __forceinline__ float2 unpack2(double a) {
    float2 f;
    asm("mov.b64 {%0, %1}, %2;" : "=f"(f.x), "=f"(f.y) : "d"(a));
    return f;
}

// ---------------------------------------------------------------------------
// Kernel 1: K-split projection GEMM. 64x64 tile, BK=16, double-buffered smem.
// ---------------------------------------------------------------------------
__global__ __launch_bounds__(256) void proj_kernel(
    const float* __restrict__ x,
    const float* __restrict__ Wl, const float* __restrict__ bl,
    const float* __restrict__ Wr, const float* __restrict__ br)
{
    __shared__ __align__(16) float As2[2][16 * 132];  // [stage][k][2m] dup pairs
    __shared__ __align__(16) float Bs[2][16 * 68];    // [stage][k][n]
    const int tid = threadIdx.x;
    const int tx = tid & 15, ty = tid >> 4;
    const int g0 = blockIdx.x * 64;
    const int n0 = blockIdx.y * 64;
    const int kh = blockIdx.z;
    const float* W    = (n0 < 256) ? Wl : Wr;
    const float* bias = (n0 < 256) ? bl : br;
    const int nw0 = (n0 < 256) ? n0 : n0 - 256;

    const int lm = tid >> 2;
    const int lk = (tid & 3) << 2;

    double acc[4][2];
#pragma unroll
    for (int i = 0; i < 4; ++i) { acc[i][0] = 0.0; acc[i][1] = 0.0; }

    const float* xp = &x[(g0 + lm) * 256 + kh * 128 + lk];
    const float* wp = &W[(nw0 + lm) * 256 + kh * 128 + lk];

    float4 av = *(const float4*)xp;
    float4 bv = *(const float4*)wp;
    {
        float* A = As2[0]; float* B = Bs[0];
        *(double*)&A[(lk + 0) * 132 + 2 * lm] = dup2(av.x);
        *(double*)&A[(lk + 1) * 132 + 2 * lm] = dup2(av.y);
        *(double*)&A[(lk + 2) * 132 + 2 * lm] = dup2(av.z);
        *(double*)&A[(lk + 3) * 132 + 2 * lm] = dup2(av.w);
        B[(lk + 0) * 68 + lm] = bv.x; B[(lk + 1) * 68 + lm] = bv.y;
        B[(lk + 2) * 68 + lm] = bv.z; B[(lk + 3) * 68 + lm] = bv.w;
    }
    av = *(const float4*)(xp + 16);
    bv = *(const float4*)(wp + 16);

#pragma unroll 1
    for (int t = 0; t < 8; ++t) {
        __syncthreads();
        if (t < 7) {
            float* A = As2[(t + 1) & 1]; float* B = Bs[(t + 1) & 1];
            *(double*)&A[(lk + 0) * 132 + 2 * lm] = dup2(av.x);
            *(double*)&A[(lk + 1) * 132 + 2 * lm] = dup2(av.y);
            *(double*)&A[(lk + 2) * 132 + 2 * lm] = dup2(av.z);
            *(double*)&A[(lk + 3) * 132 + 2 * lm] = dup2(av.w);
            B[(lk + 0) * 68 + lm] = bv.x; B[(lk + 1) * 68 + lm] = bv.y;
            B[(lk + 2) * 68 + lm] = bv.z; B[(lk + 3) * 68 + lm] = bv.w;
        }
        if (t < 6) {
            av = *(const float4*)(xp + (t + 2) * 16);
            bv = *(const float4*)(wp + (t + 2) * 16);
        }
        const float* A = As2[t & 1]; const float* B = Bs[t & 1];
#pragma unroll
        for (int k = 0; k < 16; ++k) {
            const double2 alo = *(const double2*)&A[k * 132 + 8 * ty];
            const double2 ahi = *(const double2*)&A[k * 132 + 8 * ty + 4];
            const double2 b2  = *(const double2*)&B[k * 68 + 4 * tx];
            acc[0][0] = fma2(alo.x, b2.x, acc[0][0]);
            acc[0][1] = fma2(alo.x, b2.y, acc[0][1]);
            acc[1][0] = fma2(alo.y, b2.x, acc[1][0]);
            acc[1][1] = fma2(alo.y, b2.y, acc[1][1]);
            acc[2][0] = fma2(ahi.x, b2.x, acc[2][0]);
            acc[2][1] = fma2(ahi.x, b2.y, acc[2][1]);
            acc[3][0] = fma2(ahi.y, b2.x, acc[3][0]);
            acc[3][1] = fma2(ahi.y, b2.y, acc[3][1]);
        }
    }

    float* dst = g_part + (size_t)kh * NTOT * 512;
#pragma unroll
    for (int i = 0; i < 4; ++i) {
        const int row = g0 + ty * 4 + i;
        const float2 p0 = unpack2(acc[i][0]);
        const float2 p1 = unpack2(acc[i][1]);
        float4 o;
        if (kh == 0) {
            o.x = p0.x + bias[nw0 + tx * 4 + 0];
            o.y = p0.y + bias[nw0 + tx * 4 + 1];
            o.z = p1.x + bias[nw0 + tx * 4 + 2];
            o.w = p1.y + bias[nw0 + tx * 4 + 3];
        } else {
            o.x = p0.x; o.y = p0.y; o.z = p1.x; o.w = p1.y;
        }
        *(float4*)&dst[row * 512 + n0 + tx * 4] = o;
    }
}

// ---------------------------------------------------------------------------
// Kernel 2: finalize. Sum K-partials -> g_xlxr; L/R dots; xr transpose g_xrT.
// Block: 32 g-rows. grid 64.
// ---------------------------------------------------------------------------
#define SLAB_S 524
#define FIN_SMEM ((32 * SLAB_S + 256) * 4)

__global__ __launch_bounds__(256) void finalize_kernel(const float* __restrict__ att)
{
    extern __shared__ float sh[];
    float* slab  = sh;                 // [32][SLAB_S]
    float* att_s = sh + 32 * SLAB_S;   // [256]
    const int tid = threadIdx.x;
    const int g0 = blockIdx.x * 32;
    const int b = g0 >> 9;
    const int j0b = g0 & 511;

    att_s[tid] = att[tid];
#pragma unroll
    for (int p = 0; p < 16; ++p) {
        const int idx = p * 256 + tid;
        const int row = idx >> 7, c4 = idx & 127;
        const size_t ga = (size_t)(g0 + row) * 512 + c4 * 4;
        float4 a = *(const float4*)&g_part[ga];
        const float4 c = *(const float4*)&g_part[(size_t)NTOT * 512 + ga];
        a.x += c.x; a.y += c.y; a.z += c.z; a.w += c.w;
        *(float4*)&g_xlxr[ga] = a;
        *(float4*)&slab[row * SLAB_S + c4 * 4] = a;
    }
    __syncthreads();

    const int w = tid >> 5, l = tid & 31;
#pragma unroll
    for (int p = 0; p < 8; ++p) {
        const int id = p * 8 + w;
        const int row = id >> 1, half = id & 1;
        float s = 0.f;
#pragma unroll
        for (int q = 0; q < 8; ++q)
            s += att_s[l + 32 * q] * slab[row * SLAB_S + half * 256 + l + 32 * q];
#pragma unroll
        for (int off = 16; off; off >>= 1) s += __shfl_xor_sync(0xffffffffu, s, off);
        if (l == 0) {
            if (half) g_R[g0 + row] = 0.6f * s;
            else      g_L[g0 + row] = 0.6f * s;
        }
    }

    // transpose xr half -> g_xrT[b][d][j]; warp writes 32 consecutive j per d
#pragma unroll
    for (int p = 0; p < 32; ++p) {
        const int idx = p * 256 + tid;      // 0..8191
        const int d = idx >> 5, jl = idx & 31;
        g_xrT[((size_t)b * 256 + d) * 512 + j0b + jl] = slab[jl * SLAB_S + 256 + d];
    }
}

// ---------------------------------------------------------------------------
// Kernel 3: FUSED pairwise scores + top-20 + softmax.
// Block = 8 i-rows x 512 j, 512 threads, grid 256.
// Thread owns j-pair (tid&255) and 4 rows ((tid>>8)*4..). f32x2 packed over j.
// alpha -> smem; warps 0..7 then run per-row top-20 from smem.
// ---------------------------------------------------------------------------
__global__ __launch_bounds__(512, 2) void pairtop_kernel(const float* __restrict__ att,
                                                         float* __restrict__ out)
{
    __shared__ double xl2d[256 * 8];   // [d][r] dup'd xl values
    __shared__ double ws2[256];        // dup'd 0.4*att
    __shared__ float  alpha_s[8 * 512];
    __shared__ float  Ls[8];

    const int tid = threadIdx.x;
    const int g0 = blockIdx.x * 8;
    const int b512 = g0 & ~511;
    const int b = b512 >> 9;

    if (tid < 256) ws2[tid] = dup2(0.4f * att[tid]);
    if (tid < 8)   Ls[tid] = g_L[g0 + tid];
#pragma unroll
    for (int q = 0; q < 4; ++q) {
        const int idx = q * 512 + tid;     // 0..2047
        const int r = idx & 7, d = idx >> 3;
        xl2d[d * 8 + r] = dup2(g_xlxr[(size_t)(g0 + r) * 512 + d]);
    }
    __syncthreads();

    const int jp = tid & 255;              // j-pair: j = 2jp, 2jp+1
    const int half = tid >> 8;             // rows half*4 .. half*4+3
    const double* __restrict__ xrp =
        (const double*)g_xrT + (size_t)b * 256 * 256 + jp;
    const float2 Rj2 = *(const float2*)&g_R[b512 + 2 * jp];

    double a0 = 0.0, a1 = 0.0, a2 = 0.0, a3 = 0.0;
#pragma unroll 8
    for (int d = 0; d < 256; ++d) {
        const double xr = xrp[(size_t)d * 256];
        const double wsd = ws2[d];
        const double2 x01 = *(const double2*)&xl2d[d * 8 + half * 4];
        const double2 x23 = *(const double2*)&xl2d[d * 8 + half * 4 + 2];
        a0 = fma2(wsd, abs2(add2(x01.x, xr)), a0);
        a1 = fma2(wsd, abs2(add2(x01.y, xr)), a1);
        a2 = fma2(wsd, abs2(add2(x23.x, xr)), a2);
        a3 = fma2(wsd, abs2(add2(x23.y, xr)), a3);
    }
    {
        const int r0 = half * 4;
        float2 f;
        f = unpack2(a0);
        *(float2*)&alpha_s[(r0 + 0) * 512 + 2 * jp] =
            make_float2(Ls[r0 + 0] + Rj2.x + f.x, Ls[r0 + 0] + Rj2.y + f.y);
        f = unpack2(a1);
        *(float2*)&alpha_s[(r0 + 1) * 512 + 2 * jp] =
            make_float2(Ls[r0 + 1] + Rj2.x + f.x, Ls[r0 + 1] + Rj2.y + f.y);
        f = unpack2(a2);
        *(float2*)&alpha_s[(r0 + 2) * 512 + 2 * jp] =
            make_float2(Ls[r0 + 2] + Rj2.x + f.x, Ls[r0 + 2] + Rj2.y + f.y);
        f = unpack2(a3);
        *(float2*)&alpha_s[(r0 + 3) * 512 + 2 * jp] =
            make_float2(Ls[r0 + 3] + Rj2.x + f.x, Ls[r0 + 3] + Rj2.y + f.y);
    }
    __syncthreads();

    // ---- top-20 + softmax: warp w (<8) handles row w, from smem ----
    const int w = tid >> 5, l = tid & 31;
    if (w < 8) {
        const float* arow = &alpha_s[w * 512];
        float v[16];
#pragma unroll
        for (int t = 0; t < 16; ++t) v[t] = arow[l + 32 * t];

        float wv = 0.f; int wj = 0;
        for (int kk = 0; kk < KSEL; ++kk) {
            float bv = -INFINITY; int bt = 0;
#pragma unroll
            for (int t = 0; t < 16; ++t)
                if (v[t] > bv) { bv = v[t]; bt = t; }   // strict > keeps lowest j
            int bj = bt * 32 + l;
#pragma unroll
            for (int off = 16; off; off >>= 1) {
                const float ov = __shfl_xor_sync(0xffffffffu, bv, off);
                const int   oj = __shfl_xor_sync(0xffffffffu, bj, off);
                if (ov > bv || (ov == bv && oj < bj)) { bv = ov; bj = oj; }
            }
            if (l == kk) { wv = bv; wj = bj; }
            const int owner = bj & 31, slot = bj >> 5;
            if (l == owner) {
#pragma unroll
                for (int t = 0; t < 16; ++t)
                    if (slot == t) v[t] = -INFINITY;
            }
        }

        const float m = __shfl_sync(0xffffffffu, wv, 0);   // largest selected
        const float e = (l < KSEL) ? expf(wv - m) : 0.f;
        float s = e;
#pragma unroll
        for (int off = 16; off; off >>= 1) s += __shfl_xor_sync(0xffffffffu, s, off);
        if (l < KSEL) {
            const int g = g0 + w;
            const int base = g * KSEL + l;
            out[base]                   = (float)g;             // index_i
            out[NTOT * KSEL + base]     = (float)(b512 + wj);   // index_j
            out[2 * NTOT * KSEL + base] = e / s;                // attention
        }
    }
}

// ---------------------------------------------------------------------------
extern "C" void kernel_launch(void* const* d_in, const int* in_sizes, int n_in,
                              void* d_out, int out_size)
{
    const float* x   = (const float*)d_in[0];
    const float* Wl  = (const float*)d_in[3];
    const float* bl  = (const float*)d_in[4];
    const float* Wr  = (const float*)d_in[5];
    const float* br  = (const float*)d_in[6];
    const float* att = (const float*)d_in[7];
    float* out = (float*)d_out;

    proj_kernel<<<dim3(32, 8, 2), 256>>>(x, Wl, bl, Wr, br);
    cudaFuncSetAttribute(finalize_kernel,
                         cudaFuncAttributeMaxDynamicSharedMemorySize, FIN_SMEM);
    finalize_kernel<<<64, 256, FIN_SMEM>>>(att);
    pairtop_kernel<<<256, 512>>>(att, out);
}

// round 7
// speedup vs baseline: 1.1384x; 1.1066x over previous
#include <cuda_runtime.h>
#include <math.h>

#define NTOT 2048          // B*N
#define KSEL 20

__device__ float  g_part[2 * NTOT * 512]; // K-split partial GEMM results
__device__ float  g_xlxr[NTOT * 512];     // [g][0:256)=xl, [256:512)=xr
__device__ float  g_xrT[4 * 256 * 512];   // [b][d][j] transposed xr
__device__ float  g_L[NTOT];
__device__ float  g_R[NTOT];

// ---------------- packed f32x2 helpers ----------------
__device__ __forceinline__ double fma2(double a, double b, double c) {
    double d;
    asm("fma.rn.f32x2 %0, %1, %2, %3;" : "=d"(d) : "d"(a), "d"(b), "d"(c));
    return d;
}
__device__ __forceinline__ double add2(double a, double b) {
    double d;
    asm("add.rn.f32x2 %0, %1, %2;" : "=d"(d) : "d"(a), "d"(b));
    return d;
}
__device__ __forceinline__ double abs2(double a) {
    return __longlong_as_double(__double_as_longlong(a) & 0x7fffffff7fffffffULL);
}
__device__ __forceinline__ double dup2(float v) {
    double d;
    asm("mov.b64 %0, {%1, %1};" : "=d"(d) : "f"(v));
    return d;
}
__device__ __forceinline__ float2 unpack2(double a) {
    float2 f;
    asm("mov.b64 {%0, %1}, %2;" : "=f"(f.x), "=f"(f.y) : "d"(a));
    return f;
}

// ---------------------------------------------------------------------------
// Kernel 1: K-split projection GEMM. Tile 128(M) x 64(N), BK=16, 256 threads,
// per-thread 8 rows x 4 cols (2 f32x2 pairs). A scalar-broadcast + reg-dup,
// B packed pairs. Double-buffered smem. grid (16, 8, 2).
// smem bytes/elem-FMA = 1.5 -> crossbar-balanced for f32x2.
// ---------------------------------------------------------------------------
__global__ __launch_bounds__(256, 3) void proj_kernel(
    const float* __restrict__ x,
    const float* __restrict__ Wl, const float* __restrict__ bl,
    const float* __restrict__ Wr, const float* __restrict__ br)
{
    __shared__ __align__(16) float As[2][16 * 132];  // [k][m], m=128 (+pad)
    __shared__ __align__(16) float Bs[2][16 * 68];   // [k][n], n=64 (+pad)
    const int tid = threadIdx.x;
    const int tx = tid & 15;          // N direction (4 cols each)
    const int ty = tid >> 4;          // M direction (8 rows each)
    const int g0 = blockIdx.x * 128;
    const int n0 = blockIdx.y * 64;
    const int kh = blockIdx.z;
    const float* W    = (n0 < 256) ? Wl : Wr;
    const float* bias = (n0 < 256) ? bl : br;
    const int nw0 = (n0 < 256) ? n0 : n0 - 256;

    // global->smem mapping
    const int lmA = tid >> 1;             // 0..127
    const int lkA = (tid & 1) * 8;        // 0 or 8
    const int lmB = tid >> 2;             // 0..63
    const int lkB = (tid & 3) * 4;        // 0,4,8,12

    const float* xp = &x[(g0 + lmA) * 256 + kh * 128 + lkA];
    const float* wp = &W[(nw0 + lmB) * 256 + kh * 128 + lkB];

    double acc[8][2];
#pragma unroll
    for (int i = 0; i < 8; ++i) { acc[i][0] = 0.0; acc[i][1] = 0.0; }

    float4 a0 = *(const float4*)xp;
    float4 a1 = *(const float4*)(xp + 4);
    float4 bv = *(const float4*)wp;
    {
        float* A = As[0]; float* B = Bs[0];
        A[(lkA + 0) * 132 + lmA] = a0.x; A[(lkA + 1) * 132 + lmA] = a0.y;
        A[(lkA + 2) * 132 + lmA] = a0.z; A[(lkA + 3) * 132 + lmA] = a0.w;
        A[(lkA + 4) * 132 + lmA] = a1.x; A[(lkA + 5) * 132 + lmA] = a1.y;
        A[(lkA + 6) * 132 + lmA] = a1.z; A[(lkA + 7) * 132 + lmA] = a1.w;
        B[(lkB + 0) * 68 + lmB] = bv.x;  B[(lkB + 1) * 68 + lmB] = bv.y;
        B[(lkB + 2) * 68 + lmB] = bv.z;  B[(lkB + 3) * 68 + lmB] = bv.w;
    }
    a0 = *(const float4*)(xp + 16);
    a1 = *(const float4*)(xp + 20);
    bv = *(const float4*)(wp + 16);

#pragma unroll 1
    for (int t = 0; t < 8; ++t) {
        __syncthreads();
        if (t < 7) {
            float* A = As[(t + 1) & 1]; float* B = Bs[(t + 1) & 1];
            A[(lkA + 0) * 132 + lmA] = a0.x; A[(lkA + 1) * 132 + lmA] = a0.y;
            A[(lkA + 2) * 132 + lmA] = a0.z; A[(lkA + 3) * 132 + lmA] = a0.w;
            A[(lkA + 4) * 132 + lmA] = a1.x; A[(lkA + 5) * 132 + lmA] = a1.y;
            A[(lkA + 6) * 132 + lmA] = a1.z; A[(lkA + 7) * 132 + lmA] = a1.w;
            B[(lkB + 0) * 68 + lmB] = bv.x;  B[(lkB + 1) * 68 + lmB] = bv.y;
            B[(lkB + 2) * 68 + lmB] = bv.z;  B[(lkB + 3) * 68 + lmB] = bv.w;
        }
        if (t < 6) {
            a0 = *(const float4*)(xp + (t + 2) * 16);
            a1 = *(const float4*)(xp + (t + 2) * 16 + 4);
            bv = *(const float4*)(wp + (t + 2) * 16);
        }
        const float* A = As[t & 1]; const float* B = Bs[t & 1];
#pragma unroll
        for (int k = 0; k < 16; ++k) {
            const float4 r0 = *(const float4*)&A[k * 132 + ty * 8];      // rows 0..3
            const float4 r1 = *(const float4*)&A[k * 132 + ty * 8 + 4];  // rows 4..7
            const double2 b2 = *(const double2*)&B[k * 68 + tx * 4];     // 2 n-pairs
            double d;
            d = dup2(r0.x); acc[0][0] = fma2(d, b2.x, acc[0][0]);
                            acc[0][1] = fma2(d, b2.y, acc[0][1]);
            d = dup2(r0.y); acc[1][0] = fma2(d, b2.x, acc[1][0]);
                            acc[1][1] = fma2(d, b2.y, acc[1][1]);
            d = dup2(r0.z); acc[2][0] = fma2(d, b2.x, acc[2][0]);
                            acc[2][1] = fma2(d, b2.y, acc[2][1]);
            d = dup2(r0.w); acc[3][0] = fma2(d, b2.x, acc[3][0]);
                            acc[3][1] = fma2(d, b2.y, acc[3][1]);
            d = dup2(r1.x); acc[4][0] = fma2(d, b2.x, acc[4][0]);
                            acc[4][1] = fma2(d, b2.y, acc[4][1]);
            d = dup2(r1.y); acc[5][0] = fma2(d, b2.x, acc[5][0]);
                            acc[5][1] = fma2(d, b2.y, acc[5][1]);
            d = dup2(r1.z); acc[6][0] = fma2(d, b2.x, acc[6][0]);
                            acc[6][1] = fma2(d, b2.y, acc[6][1]);
            d = dup2(r1.w); acc[7][0] = fma2(d, b2.x, acc[7][0]);
                            acc[7][1] = fma2(d, b2.y, acc[7][1]);
        }
    }

    float* dst = g_part + (size_t)kh * NTOT * 512;
#pragma unroll
    for (int i = 0; i < 8; ++i) {
        const int row = g0 + ty * 8 + i;
        const float2 p0 = unpack2(acc[i][0]);
        const float2 p1 = unpack2(acc[i][1]);
        float4 o;
        if (kh == 0) {
            o.x = p0.x + bias[nw0 + tx * 4 + 0];
            o.y = p0.y + bias[nw0 + tx * 4 + 1];
            o.z = p1.x + bias[nw0 + tx * 4 + 2];
            o.w = p1.y + bias[nw0 + tx * 4 + 3];
        } else {
            o.x = p0.x; o.y = p0.y; o.z = p1.x; o.w = p1.y;
        }
        *(float4*)&dst[row * 512 + n0 + tx * 4] = o;
    }
}

// ---------------------------------------------------------------------------
// Kernel 2: finalize. Sum K-partials -> g_xlxr; L/R dots; xr transpose g_xrT.
// ---------------------------------------------------------------------------
#define SLAB_S 524
#define FIN_SMEM ((32 * SLAB_S + 256) * 4)

__global__ __launch_bounds__(256) void finalize_kernel(const float* __restrict__ att)
{
    extern __shared__ float sh[];
    float* slab  = sh;                 // [32][SLAB_S]
    float* att_s = sh + 32 * SLAB_S;   // [256]
    const int tid = threadIdx.x;
    const int g0 = blockIdx.x * 32;
    const int b = g0 >> 9;
    const int j0b = g0 & 511;

    att_s[tid] = att[tid];
#pragma unroll
    for (int p = 0; p < 16; ++p) {
        const int idx = p * 256 + tid;
        const int row = idx >> 7, c4 = idx & 127;
        const size_t ga = (size_t)(g0 + row) * 512 + c4 * 4;
        float4 a = *(const float4*)&g_part[ga];
        const float4 c = *(const float4*)&g_part[(size_t)NTOT * 512 + ga];
        a.x += c.x; a.y += c.y; a.z += c.z; a.w += c.w;
        *(float4*)&g_xlxr[ga] = a;
        *(float4*)&slab[row * SLAB_S + c4 * 4] = a;
    }
    __syncthreads();

    const int w = tid >> 5, l = tid & 31;
#pragma unroll
    for (int p = 0; p < 8; ++p) {
        const int id = p * 8 + w;
        const int row = id >> 1, half = id & 1;
        float s = 0.f;
#pragma unroll
        for (int q = 0; q < 8; ++q)
            s += att_s[l + 32 * q] * slab[row * SLAB_S + half * 256 + l + 32 * q];
#pragma unroll
        for (int off = 16; off; off >>= 1) s += __shfl_xor_sync(0xffffffffu, s, off);
        if (l == 0) {
            if (half) g_R[g0 + row] = 0.6f * s;
            else      g_L[g0 + row] = 0.6f * s;
        }
    }

    // transpose xr half -> g_xrT[b][d][j]
#pragma unroll
    for (int p = 0; p < 32; ++p) {
        const int idx = p * 256 + tid;      // 0..8191
        const int d = idx >> 5, jl = idx & 31;
        g_xrT[((size_t)b * 256 + d) * 512 + j0b + jl] = slab[jl * SLAB_S + 256 + d];
    }
}

// ---------------------------------------------------------------------------
// Kernel 3: FUSED pairwise scores + top-20 + softmax.
// 256 threads; thread owns j-pair tid and ALL 8 i-rows (acc in regs).
// grid 256, 3 blocks/SM (85-reg cap -> no spills). alpha -> smem -> topk.
// ---------------------------------------------------------------------------
__global__ __launch_bounds__(256, 3) void pairtop_kernel(const float* __restrict__ att,
                                                         float* __restrict__ out)
{
    __shared__ double xl2d[256 * 8];   // [d][r] dup'd xl, 16KB
    __shared__ double ws2[256];        // dup'd 0.4*att, 2KB
    __shared__ float  alpha_s[8 * 512];
    __shared__ float  Ls[8];

    const int tid = threadIdx.x;
    const int g0 = blockIdx.x * 8;
    const int b512 = g0 & ~511;
    const int b = b512 >> 9;

    ws2[tid] = dup2(0.4f * att[tid]);
    if (tid < 8) Ls[tid] = g_L[g0 + tid];
#pragma unroll
    for (int q = 0; q < 8; ++q) {
        const int idx = q * 256 + tid;     // 0..2047
        const int r = idx & 7, d = idx >> 3;
        xl2d[d * 8 + r] = dup2(g_xlxr[(size_t)(g0 + r) * 512 + d]);
    }
    __syncthreads();

    const int jp = tid;                    // j-pair: j = 2jp, 2jp+1
    const double* __restrict__ xrp =
        (const double*)g_xrT + (size_t)b * 256 * 256 + jp;
    const float2 Rj2 = *(const float2*)&g_R[b512 + 2 * jp];

    double acc[8];
#pragma unroll
    for (int i = 0; i < 8; ++i) acc[i] = 0.0;

#pragma unroll 1
    for (int c = 0; c < 64; ++c) {         // 4 d per chunk
        double xr[4];
#pragma unroll
        for (int q = 0; q < 4; ++q)
            xr[q] = xrp[(size_t)(c * 4 + q) * 256];
#pragma unroll
        for (int q = 0; q < 4; ++q) {
            const int d = c * 4 + q;
            const double wsd = ws2[d];
            const double2 x01 = *(const double2*)&xl2d[d * 8 + 0];
            const double2 x23 = *(const double2*)&xl2d[d * 8 + 2];
            const double2 x45 = *(const double2*)&xl2d[d * 8 + 4];
            const double2 x67 = *(const double2*)&xl2d[d * 8 + 6];
            acc[0] = fma2(wsd, abs2(add2(x01.x, xr[q])), acc[0]);
            acc[1] = fma2(wsd, abs2(add2(x01.y, xr[q])), acc[1]);
            acc[2] = fma2(wsd, abs2(add2(x23.x, xr[q])), acc[2]);
            acc[3] = fma2(wsd, abs2(add2(x23.y, xr[q])), acc[3]);
            acc[4] = fma2(wsd, abs2(add2(x45.x, xr[q])), acc[4]);
            acc[5] = fma2(wsd, abs2(add2(x45.y, xr[q])), acc[5]);
            acc[6] = fma2(wsd, abs2(add2(x67.x, xr[q])), acc[6]);
            acc[7] = fma2(wsd, abs2(add2(x67.y, xr[q])), acc[7]);
        }
    }
#pragma unroll
    for (int r = 0; r < 8; ++r) {
        const float2 f = unpack2(acc[r]);
        *(float2*)&alpha_s[r * 512 + 2 * jp] =
            make_float2(Ls[r] + Rj2.x + f.x, Ls[r] + Rj2.y + f.y);
    }
    __syncthreads();

    // ---- top-20 + softmax: warp w handles row w, from smem ----
    const int w = tid >> 5, l = tid & 31;
    const float* arow = &alpha_s[w * 512];
    float v[16];
#pragma unroll
    for (int t = 0; t < 16; ++t) v[t] = arow[l + 32 * t];

    float wv = 0.f; int wj = 0;
    for (int kk = 0; kk < KSEL; ++kk) {
        float bv = -INFINITY; int bt = 0;
#pragma unroll
        for (int t = 0; t < 16; ++t)
            if (v[t] > bv) { bv = v[t]; bt = t; }   // strict > keeps lowest j
        int bj = bt * 32 + l;
#pragma unroll
        for (int off = 16; off; off >>= 1) {
            const float ov = __shfl_xor_sync(0xffffffffu, bv, off);
            const int   oj = __shfl_xor_sync(0xffffffffu, bj, off);
            if (ov > bv || (ov == bv && oj < bj)) { bv = ov; bj = oj; }
        }
        if (l == kk) { wv = bv; wj = bj; }
        const int owner = bj & 31, slot = bj >> 5;
        if (l == owner) {
#pragma unroll
            for (int t = 0; t < 16; ++t)
                if (slot == t) v[t] = -INFINITY;
        }
    }

    const float m = __shfl_sync(0xffffffffu, wv, 0);   // largest selected
    const float e = (l < KSEL) ? expf(wv - m) : 0.f;
    float s = e;
#pragma unroll
    for (int off = 16; off; off >>= 1) s += __shfl_xor_sync(0xffffffffu, s, off);
    if (l < KSEL) {
        const int g = g0 + w;
        const int base = g * KSEL + l;
        out[base]                   = (float)g;             // index_i
        out[NTOT * KSEL + base]     = (float)(b512 + wj);   // index_j
        out[2 * NTOT * KSEL + base] = e / s;                // attention
    }
}

// ---------------------------------------------------------------------------
extern "C" void kernel_launch(void* const* d_in, const int* in_sizes, int n_in,
                              void* d_out, int out_size)
{
    const float* x   = (const float*)d_in[0];
    const float* Wl  = (const float*)d_in[3];
    const float* bl  = (const float*)d_in[4];
    const float* Wr  = (const float*)d_in[5];
    const float* br  = (const float*)d_in[6];
    const float* att = (const float*)d_in[7];
    float* out = (float*)d_out;

    proj_kernel<<<dim3(16, 8, 2), 256>>>(x, Wl, bl, Wr, br);
    cudaFuncSetAttribute(finalize_kernel,
                         cudaFuncAttributeMaxDynamicSharedMemorySize, FIN_SMEM);
    finalize_kernel<<<64, 256, FIN_SMEM>>>(att);
    pairtop_kernel<<<256, 256>>>(att, out);
}